// round 3
// baseline (speedup 1.0000x reference)
#include <cuda_runtime.h>

#define AA 512      // attention length
#define OUTS 512    // out_size
#define HH 512
#define WW 512
#define CC 3
#define NMAX 32

// scratch (allocation-free rule: device globals)
__device__ float g_px[NMAX * OUTS];
__device__ float g_py[NMAX * OUTS];

__device__ __forceinline__ float warpSum(float v) {
    #pragma unroll
    for (int o = 16; o; o >>= 1) v += __shfl_xor_sync(0xffffffffu, v, o);
    return v;
}
__device__ __forceinline__ float warpMax(float v) {
    #pragma unroll
    for (int o = 16; o; o >>= 1) v = fmaxf(v, __shfl_xor_sync(0xffffffffu, v, o));
    return v;
}

// fused block reductions for two values (512 threads), one barrier pair each
__device__ void blockSum2(float a, float b, volatile float* sbuf, float* ra, float* rb) {
    int lane = threadIdx.x & 31, w = threadIdx.x >> 5;
    a = warpSum(a); b = warpSum(b);
    if (lane == 0) { sbuf[w] = a; sbuf[32 + w] = b; }
    __syncthreads();
    if (w == 0) {
        float x = (lane < 16) ? sbuf[lane] : 0.f;
        float y = (lane < 16) ? sbuf[32 + lane] : 0.f;
        x = warpSum(x); y = warpSum(y);
        if (lane == 0) { sbuf[0] = x; sbuf[32] = y; }
    }
    __syncthreads();
    *ra = sbuf[0]; *rb = sbuf[32];
    __syncthreads();
}

__device__ void blockMax2(float a, float b, volatile float* sbuf, float* ra, float* rb) {
    int lane = threadIdx.x & 31, w = threadIdx.x >> 5;
    a = warpMax(a); b = warpMax(b);
    if (lane == 0) { sbuf[w] = a; sbuf[32 + w] = b; }
    __syncthreads();
    if (w == 0) {
        float x = (lane < 16) ? sbuf[lane] : -3.4e38f;
        float y = (lane < 16) ? sbuf[32 + lane] : -3.4e38f;
        x = warpMax(x); y = warpMax(y);
        if (lane == 0) { sbuf[0] = x; sbuf[32] = y; }
    }
    __syncthreads();
    *ra = sbuf[0]; *rb = sbuf[32];
    __syncthreads();
}

// fused inclusive block scan of two 512-value sequences -> outa[tid], outb[tid]
__device__ void blockScan2(float a, float b, float* outa, float* outb, volatile float* sbuf) {
    int lane = threadIdx.x & 31, w = threadIdx.x >> 5;
    float sa = a, sb = b;
    #pragma unroll
    for (int o = 1; o < 32; o <<= 1) {
        float ta = __shfl_up_sync(0xffffffffu, sa, o);
        float tb = __shfl_up_sync(0xffffffffu, sb, o);
        if (lane >= o) { sa += ta; sb += tb; }
    }
    if (lane == 31) { sbuf[w] = sa; sbuf[32 + w] = sb; }
    __syncthreads();
    if (w == 0 && lane < 16) {
        float wa = sbuf[lane], wb = sbuf[32 + lane];
        #pragma unroll
        for (int o = 1; o < 16; o <<= 1) {
            float ta = __shfl_up_sync(0x0000ffffu, wa, o);
            float tb = __shfl_up_sync(0x0000ffffu, wb, o);
            if (lane >= o) { wa += ta; wb += tb; }
        }
        sbuf[lane] = wa; sbuf[32 + lane] = wb;
    }
    __syncthreads();
    float offa = (w > 0) ? sbuf[w - 1] : 0.f;
    float offb = (w > 0) ? sbuf[32 + w - 1] : 0.f;
    outa[threadIdx.x] = sa + offa;
    outb[threadIdx.x] = sb + offb;
    __syncthreads();
}

__device__ __forceinline__ float inv_cdf_one(const float* c, float tk) {
    // searchsorted left: first j with c[j] >= tk.
    // Range [0,512] has size 513 -> needs exactly 10 halvings.
    int l = 0, h = AA;
    #pragma unroll
    for (int it = 0; it < 10; ++it) {
        if (l < h) {
            int m = (l + h) >> 1;
            if (c[m] < tk) l = m + 1; else h = m;
        }
    }
    int j = min(l, AA - 1);
    float cp = (j > 0) ? c[j - 1] : 0.f;
    float dens = c[j] - cp;
    float p = (float)j + (tk - cp) / fmaxf(dens, 1e-6f);
    return 2.f * p / (float)AA - 1.f;
}

__global__ void __launch_bounds__(512) prep_kernel(const float* __restrict__ attx,
                                                   const float* __restrict__ atty) {
    __shared__ float sbuf[64];
    __shared__ float cx[AA];
    __shared__ float cy[AA];
    int n = blockIdx.x;
    int t = threadIdx.x;

    float ax = attx[n * AA + t];
    float ay = atty[n * AA + t];

    float sax, say;
    blockSum2(ax, ay, sbuf, &sax, &say);
    ax = ax / sax * (float)OUTS;
    ay = ay / say * (float)OUTS;

    const float thr0 = 4.0f * (float)OUTS / (float)AA;  // DENSE*out/A
    #pragma unroll
    for (int it = 0; it < 5; ++it) {
        float mx, my;
        blockMax2(ax, ay, sbuf, &mx, &my);
        float tt = fminf(mx, my);
        if (it == 0) tt = fminf(tt, thr0);
        ax = fminf(ax, tt);
        ay = fminf(ay, tt);
        blockSum2(ax, ay, sbuf, &sax, &say);
        ax += ((float)OUTS - sax) / (float)AA;
        ay += ((float)OUTS - say) / (float)AA;
    }

    blockScan2(ax, ay, cx, cy, sbuf);

    float stepx = cx[AA - 1] / (float)OUTS;
    float stepy = cy[AA - 1] / (float)OUTS;
    float tkx = ((float)t + 0.5f) * stepx;
    float tky = ((float)t + 0.5f) * stepy;

    g_px[n * OUTS + t] = inv_cdf_one(cx, tkx);
    g_py[n * OUTS + t] = inv_cdf_one(cy, tky);
}

// one block = one output row (n, i). All pixels of the row share source rows y0,y1.
__global__ void __launch_bounds__(512) sample_kernel(const float* __restrict__ data,
                                                     float* __restrict__ out_s,
                                                     float2* __restrict__ out_g) {
    __shared__ float rows[2][CC][WW];   // 12 KB

    int t = threadIdx.x;
    int i = blockIdx.x;
    int n = blockIdx.y;

    float py = __ldg(&g_py[n * OUTS + i]);
    float iy = (py + 1.f) * 0.5f * (float)(HH - 1);
    float fy = floorf(iy);
    float wy = iy - fy;
    int y0 = min(max((int)fy, 0), HH - 1);
    int y1 = min(y0 + 1, HH - 1);

    // stage rows y0,y1 of all channels, fully coalesced float4
    const float* img = data + (size_t)n * CC * HH * WW;
    {
        // 2 rows * 3 channels * 128 float4 = 768 float4 chunks
        #pragma unroll
        for (int idx = t; idx < 2 * CC * (WW / 4); idx += 512) {
            int r = idx / (CC * (WW / 4));
            int rem = idx - r * (CC * (WW / 4));
            int c = rem / (WW / 4);
            int q = rem - c * (WW / 4);
            int y = r ? y1 : y0;
            const float4* src = (const float4*)(img + ((size_t)c * HH + y) * WW);
            ((float4*)rows[r][c])[q] = __ldg(src + q);
        }
    }
    __syncthreads();

    int j = t;
    float px = __ldg(&g_px[n * OUTS + j]);
    float ix = (px + 1.f) * 0.5f * (float)(WW - 1);
    float fx = floorf(ix);
    float wx = ix - fx;
    int x0 = min(max((int)fx, 0), WW - 1);
    int x1 = min(x0 + 1, WW - 1);

    float omwx = 1.f - wx, omwy = 1.f - wy;
    float* o = out_s + (((size_t)n * CC) * HH + i) * WW + j;

    #pragma unroll
    for (int c = 0; c < CC; ++c) {
        float v00 = rows[0][c][x0];
        float v01 = rows[0][c][x1];
        float v10 = rows[1][c][x0];
        float v11 = rows[1][c][x1];
        float top = v00 * omwx + v01 * wx;
        float bot = v10 * omwx + v11 * wx;
        o[(size_t)c * HH * WW] = top * omwy + bot * wy;
    }

    out_g[((size_t)n * OUTS + i) * OUTS + j] = make_float2(px, py);
}

extern "C" void kernel_launch(void* const* d_in, const int* in_sizes, int n_in,
                              void* d_out, int out_size) {
    const float* data = (const float*)d_in[0];
    const float* attx = (const float*)d_in[1];
    const float* atty = (const float*)d_in[2];

    int N = in_sizes[1] / AA;   // attx is (N, 512, 1)

    float* out = (float*)d_out;
    float* out_s = out;                                        // (N, C, 512, 512)
    float2* out_g = (float2*)(out + (size_t)N * CC * HH * WW); // (N, 512, 512, 2)

    prep_kernel<<<N, 512>>>(attx, atty);
    dim3 grid(OUTS, N);
    sample_kernel<<<grid, 512>>>(data, out_s, out_g);
}

// round 4
// speedup vs baseline: 1.1354x; 1.1354x over previous
#include <cuda_runtime.h>

#define AA 512      // attention length
#define OUTS 512    // out_size
#define HH 512
#define WW 512
#define CC 3
#define NMAX 32

// scratch (allocation-free rule: device globals)
__device__ float g_px[NMAX * OUTS];
__device__ float g_py[NMAX * OUTS];

__device__ __forceinline__ float warpSum(float v) {
    #pragma unroll
    for (int o = 16; o; o >>= 1) v += __shfl_xor_sync(0xffffffffu, v, o);
    return v;
}
__device__ __forceinline__ float warpMax(float v) {
    #pragma unroll
    for (int o = 16; o; o >>= 1) v = fmaxf(v, __shfl_xor_sync(0xffffffffu, v, o));
    return v;
}

// fused block reductions for two values (512 threads), one barrier pair each
__device__ void blockSum2(float a, float b, volatile float* sbuf, float* ra, float* rb) {
    int lane = threadIdx.x & 31, w = threadIdx.x >> 5;
    a = warpSum(a); b = warpSum(b);
    if (lane == 0) { sbuf[w] = a; sbuf[32 + w] = b; }
    __syncthreads();
    if (w == 0) {
        float x = (lane < 16) ? sbuf[lane] : 0.f;
        float y = (lane < 16) ? sbuf[32 + lane] : 0.f;
        x = warpSum(x); y = warpSum(y);
        if (lane == 0) { sbuf[0] = x; sbuf[32] = y; }
    }
    __syncthreads();
    *ra = sbuf[0]; *rb = sbuf[32];
    __syncthreads();
}

__device__ void blockMax2(float a, float b, volatile float* sbuf, float* ra, float* rb) {
    int lane = threadIdx.x & 31, w = threadIdx.x >> 5;
    a = warpMax(a); b = warpMax(b);
    if (lane == 0) { sbuf[w] = a; sbuf[32 + w] = b; }
    __syncthreads();
    if (w == 0) {
        float x = (lane < 16) ? sbuf[lane] : -3.4e38f;
        float y = (lane < 16) ? sbuf[32 + lane] : -3.4e38f;
        x = warpMax(x); y = warpMax(y);
        if (lane == 0) { sbuf[0] = x; sbuf[32] = y; }
    }
    __syncthreads();
    *ra = sbuf[0]; *rb = sbuf[32];
    __syncthreads();
}

// fused inclusive block scan of two 512-value sequences -> outa[tid], outb[tid]
__device__ void blockScan2(float a, float b, float* outa, float* outb, volatile float* sbuf) {
    int lane = threadIdx.x & 31, w = threadIdx.x >> 5;
    float sa = a, sb = b;
    #pragma unroll
    for (int o = 1; o < 32; o <<= 1) {
        float ta = __shfl_up_sync(0xffffffffu, sa, o);
        float tb = __shfl_up_sync(0xffffffffu, sb, o);
        if (lane >= o) { sa += ta; sb += tb; }
    }
    if (lane == 31) { sbuf[w] = sa; sbuf[32 + w] = sb; }
    __syncthreads();
    if (w == 0 && lane < 16) {
        float wa = sbuf[lane], wb = sbuf[32 + lane];
        #pragma unroll
        for (int o = 1; o < 16; o <<= 1) {
            float ta = __shfl_up_sync(0x0000ffffu, wa, o);
            float tb = __shfl_up_sync(0x0000ffffu, wb, o);
            if (lane >= o) { wa += ta; wb += tb; }
        }
        sbuf[lane] = wa; sbuf[32 + lane] = wb;
    }
    __syncthreads();
    float offa = (w > 0) ? sbuf[w - 1] : 0.f;
    float offb = (w > 0) ? sbuf[32 + w - 1] : 0.f;
    outa[threadIdx.x] = sa + offa;
    outb[threadIdx.x] = sb + offb;
    __syncthreads();
}

__device__ __forceinline__ float inv_cdf_one(const float* c, float tk) {
    // searchsorted left: first j with c[j] >= tk.
    // Range [0,512] has size 513 -> needs exactly 10 halvings.
    int l = 0, h = AA;
    #pragma unroll
    for (int it = 0; it < 10; ++it) {
        if (l < h) {
            int m = (l + h) >> 1;
            if (c[m] < tk) l = m + 1; else h = m;
        }
    }
    int j = min(l, AA - 1);
    float cp = (j > 0) ? c[j - 1] : 0.f;
    float dens = c[j] - cp;
    float p = (float)j + (tk - cp) / fmaxf(dens, 1e-6f);
    return 2.f * p / (float)AA - 1.f;
}

__global__ void __launch_bounds__(512) prep_kernel(const float* __restrict__ attx,
                                                   const float* __restrict__ atty) {
    __shared__ float sbuf[64];
    __shared__ float cx[AA];
    __shared__ float cy[AA];
    int n = blockIdx.x;
    int t = threadIdx.x;

    float ax = attx[n * AA + t];
    float ay = atty[n * AA + t];

    float sax, say;
    blockSum2(ax, ay, sbuf, &sax, &say);
    ax = ax / sax * (float)OUTS;
    ay = ay / say * (float)OUTS;

    const float thr0 = 4.0f * (float)OUTS / (float)AA;  // DENSE*out/A
    #pragma unroll
    for (int it = 0; it < 5; ++it) {
        float mx, my;
        blockMax2(ax, ay, sbuf, &mx, &my);
        float tt = fminf(mx, my);
        if (it == 0) tt = fminf(tt, thr0);
        ax = fminf(ax, tt);
        ay = fminf(ay, tt);
        blockSum2(ax, ay, sbuf, &sax, &say);
        ax += ((float)OUTS - sax) / (float)AA;
        ay += ((float)OUTS - say) / (float)AA;
    }

    blockScan2(ax, ay, cx, cy, sbuf);

    float stepx = cx[AA - 1] / (float)OUTS;
    float stepy = cy[AA - 1] / (float)OUTS;
    float tkx = ((float)t + 0.5f) * stepx;
    float tky = ((float)t + 0.5f) * stepy;

    g_px[n * OUTS + t] = inv_cdf_one(cx, tkx);
    g_py[n * OUTS + t] = inv_cdf_one(cy, tky);
}

// direct-gather sampler: each thread computes 4 consecutive j pixels of one row.
// block (128,4): tx = pixel group, ty = row within group of 4. grid (OUTS/4, N).
__global__ void __launch_bounds__(512) sample_kernel(const float* __restrict__ data,
                                                     float* __restrict__ out_s,
                                                     float4* __restrict__ out_g) {
    int tx = threadIdx.x;                 // 0..127
    int i = blockIdx.x * 4 + threadIdx.y; // output row
    int n = blockIdx.y;
    int j0 = tx << 2;                     // first of 4 pixels

    float py = __ldg(&g_py[n * OUTS + i]);
    float iy = (py + 1.f) * 0.5f * (float)(HH - 1);
    float fy = floorf(iy);
    float wy = iy - fy;
    int y0 = min(max((int)fy, 0), HH - 1);
    int y1 = min(y0 + 1, HH - 1);

    float4 px4 = __ldg((const float4*)&g_px[n * OUTS + j0]);
    float pxv[4] = {px4.x, px4.y, px4.z, px4.w};

    int x0[4], x1[4];
    float wx[4];
    #pragma unroll
    for (int k = 0; k < 4; ++k) {
        float ix = (pxv[k] + 1.f) * 0.5f * (float)(WW - 1);
        float fx = floorf(ix);
        wx[k] = ix - fx;
        x0[k] = min(max((int)fx, 0), WW - 1);
        x1[k] = min(x0[k] + 1, WW - 1);
    }

    const float* img = data + (size_t)n * CC * HH * WW;
    float omwy = 1.f - wy;

    float acc[CC][4];
    #pragma unroll
    for (int c = 0; c < CC; ++c) {
        const float* r0 = img + ((size_t)c * HH + y0) * WW;
        const float* r1 = img + ((size_t)c * HH + y1) * WW;
        #pragma unroll
        for (int k = 0; k < 4; ++k) {
            float v00 = __ldg(r0 + x0[k]);
            float v01 = __ldg(r0 + x1[k]);
            float v10 = __ldg(r1 + x0[k]);
            float v11 = __ldg(r1 + x1[k]);
            float omwx = 1.f - wx[k];
            float top = v00 * omwx + v01 * wx[k];
            float bot = v10 * omwx + v11 * wx[k];
            acc[c][k] = top * omwy + bot * wy;
        }
    }

    float* o = out_s + (((size_t)n * CC) * HH + i) * WW + j0;
    #pragma unroll
    for (int c = 0; c < CC; ++c) {
        *((float4*)(o + (size_t)c * HH * WW)) =
            make_float4(acc[c][0], acc[c][1], acc[c][2], acc[c][3]);
    }

    size_t gbase = (((size_t)n * OUTS + i) * OUTS + j0) >> 1;  // in float4 units
    out_g[gbase]     = make_float4(pxv[0], py, pxv[1], py);
    out_g[gbase + 1] = make_float4(pxv[2], py, pxv[3], py);
}

extern "C" void kernel_launch(void* const* d_in, const int* in_sizes, int n_in,
                              void* d_out, int out_size) {
    const float* data = (const float*)d_in[0];
    const float* attx = (const float*)d_in[1];
    const float* atty = (const float*)d_in[2];

    int N = in_sizes[1] / AA;   // attx is (N, 512, 1)

    float* out = (float*)d_out;
    float* out_s = out;                                        // (N, C, 512, 512)
    float4* out_g = (float4*)(out + (size_t)N * CC * HH * WW); // (N, 512, 512, 2)

    prep_kernel<<<N, 512>>>(attx, atty);
    dim3 block(128, 4);
    dim3 grid(OUTS / 4, N);
    sample_kernel<<<grid, block>>>(data, out_s, out_g);
}